// round 1
// baseline (speedup 1.0000x reference)
#include <cuda_runtime.h>
#include <cuda_bf16.h>

// ---------------------------------------------------------------------------
// Attention_9947144257674  — fp32 baseline
//   B=4, S=2048, D_MODEL=1024, N_HEADS=16, D_HEAD=64
//   inputs: x, W_Q, b_Q, W_K, b_K, W_V, b_V, W_O, b_O   (all fp32)
//   out:    [B, S, D_MODEL] fp32
//
// Stage 1: QKV projection  q/k/v[bs][n*64+h] = x[bs] . W[n][:,h] + b[n][h]
// Stage 2: causal flash attention per (b, head), z[bs][n*64+h]
// Stage 3: output projection  out[bs][e] = z[bs] . W_O(flat 1024x1024) + b_O
// ---------------------------------------------------------------------------

#define BSROWS 8192        // B*S
#define DM     1024

// scratch (device globals: allocation-guard safe)
__device__ float g_q[(size_t)BSROWS * DM];
__device__ float g_k[(size_t)BSROWS * DM];
__device__ float g_v[(size_t)BSROWS * DM];
__device__ float g_z[(size_t)BSROWS * DM];

// ---------------------------------------------------------------------------
// Stage 1: fused QKV GEMM.  M=8192, K=1024, N=1024 per matrix.
// Weight layout W[n][e][h] -> for output column c = n*64+h (tile never crosses
// a 64-col head boundary since BN=64): element = W[(c>>6)<<16 | e<<6 | (c&63)].
// Tiles: BM=64, BN=64, BK=16, 256 threads, 4x4 per-thread microtile.
// ---------------------------------------------------------------------------
__global__ __launch_bounds__(256) void qkv_gemm(
    const float* __restrict__ x,
    const float* __restrict__ WQ, const float* __restrict__ bQ,
    const float* __restrict__ WK, const float* __restrict__ bK,
    const float* __restrict__ WV, const float* __restrict__ bV)
{
    const float* W;
    const float* bias;
    float* C;
    if (blockIdx.z == 0)      { W = WQ; bias = bQ; C = g_q; }
    else if (blockIdx.z == 1) { W = WK; bias = bK; C = g_k; }
    else                      { W = WV; bias = bV; C = g_v; }

    __shared__ float As[16][64];   // [k][m] (transposed on load)
    __shared__ float Bs[16][64];   // [k][n]

    const int bm  = blockIdx.y * 64;
    const int bn  = blockIdx.x * 64;
    const int tid = threadIdx.x;
    const int tx  = tid & 15;
    const int ty  = tid >> 4;

    // head-block base: bn is a multiple of 64, so head index = bn>>6
    const float* Wg = W + ((size_t)(bn >> 6) << 16);

    float acc[4][4] = {};

    for (int k0 = 0; k0 < 1024; k0 += 16) {
        {
            // A tile: 64 rows x 16 k, one float4 per thread
            int row = tid >> 2;
            int col = (tid & 3) * 4;
            float4 va = *reinterpret_cast<const float4*>(
                x + (size_t)(bm + row) * 1024 + k0 + col);
            As[col + 0][row] = va.x;
            As[col + 1][row] = va.y;
            As[col + 2][row] = va.z;
            As[col + 3][row] = va.w;
            // B tile: 16 k x 64 n, one float4 per thread
            int kr = tid >> 4;
            int nc = (tid & 15) * 4;
            *reinterpret_cast<float4*>(&Bs[kr][nc]) =
                *reinterpret_cast<const float4*>(Wg + (size_t)(k0 + kr) * 64 + nc);
        }
        __syncthreads();

        #pragma unroll
        for (int kk = 0; kk < 16; kk++) {
            float4 a = *reinterpret_cast<const float4*>(&As[kk][ty * 4]);
            float4 b = *reinterpret_cast<const float4*>(&Bs[kk][tx * 4]);
            float av[4] = {a.x, a.y, a.z, a.w};
            float bv[4] = {b.x, b.y, b.z, b.w};
            #pragma unroll
            for (int i = 0; i < 4; i++)
                #pragma unroll
                for (int j = 0; j < 4; j++)
                    acc[i][j] += av[i] * bv[j];
        }
        __syncthreads();
    }

    #pragma unroll
    for (int i = 0; i < 4; i++) {
        const int r = bm + ty * 4 + i;
        #pragma unroll
        for (int j = 0; j < 4; j++) {
            const int c = bn + tx * 4 + j;
            C[(size_t)r * 1024 + c] = acc[i][j] + bias[c];
        }
    }
}

// ---------------------------------------------------------------------------
// Stage 2: causal flash attention, fp32.
// grid = (S/64, B*N_HEADS), block = 256.
// BQ=64 queries per block, BK=32 keys per inner tile, online softmax.
// Per-thread: 4 q-rows (ty), 4 h-cols (tx) output accumulator.
// ---------------------------------------------------------------------------
__global__ __launch_bounds__(256) void attn_kernel()
{
    const int qt = blockIdx.x;                   // query tile (64 wide)
    const int b  = blockIdx.y >> 4;
    const int n  = blockIdx.y & 15;

    __shared__ float Qs[64][68];
    __shared__ float Ks[32][68];
    __shared__ float Vs[32][68];
    __shared__ float Ss[64][36];
    __shared__ float alpha_s[64];
    __shared__ float l_s[64];

    const int tid = threadIdx.x;
    const int tx  = tid & 15;
    const int ty  = tid >> 4;

    const size_t head_off = (size_t)n * 64;
    const float* qbase = g_q + ((size_t)b * 2048 + (size_t)qt * 64) * 1024 + head_off;

    // load Q tile: 64 x 64 = 1024 float4 slots, 4 per thread
    #pragma unroll
    for (int it = 0; it < 4; it++) {
        int s   = tid + it * 256;
        int row = s >> 4;
        int c4  = (s & 15) * 4;
        *reinterpret_cast<float4*>(&Qs[row][c4]) =
            *reinterpret_cast<const float4*>(qbase + (size_t)row * 1024 + c4);
    }

    float m_r = -1e30f, l_r = 0.f;   // only tid<64 uses these
    float acc[4][4] = {};

    const int nkt = 2 * qt + 2;      // causal: keys up to (qt+1)*64
    for (int kt = 0; kt < nkt; kt++) {
        const float* kbase = g_k + ((size_t)b * 2048 + (size_t)kt * 32) * 1024 + head_off;
        const float* vbase = g_v + ((size_t)b * 2048 + (size_t)kt * 32) * 1024 + head_off;

        __syncthreads();   // previous iter's reads of Ks/Vs/Ss/alpha_s done
        #pragma unroll
        for (int it = 0; it < 2; it++) {
            int s   = tid + it * 256;         // 0..511
            int row = s >> 4;
            int c4  = (s & 15) * 4;
            *reinterpret_cast<float4*>(&Ks[row][c4]) =
                *reinterpret_cast<const float4*>(kbase + (size_t)row * 1024 + c4);
            *reinterpret_cast<float4*>(&Vs[row][c4]) =
                *reinterpret_cast<const float4*>(vbase + (size_t)row * 1024 + c4);
        }
        __syncthreads();

        // S = Q K^T for 64x32 tile; thread does 4 rows x 2 cols
        float sv[4][2] = {};
        #pragma unroll
        for (int h4 = 0; h4 < 64; h4 += 4) {
            float4 aq[4], bk[2];
            #pragma unroll
            for (int i = 0; i < 4; i++)
                aq[i] = *reinterpret_cast<const float4*>(&Qs[ty * 4 + i][h4]);
            #pragma unroll
            for (int j = 0; j < 2; j++)
                bk[j] = *reinterpret_cast<const float4*>(&Ks[tx * 2 + j][h4]);
            #pragma unroll
            for (int i = 0; i < 4; i++) {
                #pragma unroll
                for (int j = 0; j < 2; j++) {
                    sv[i][j] += aq[i].x * bk[j].x;
                    sv[i][j] += aq[i].y * bk[j].y;
                    sv[i][j] += aq[i].z * bk[j].z;
                    sv[i][j] += aq[i].w * bk[j].w;
                }
            }
        }
        // scale + causal mask (EPSILON = -1e5 like the reference), write to smem
        #pragma unroll
        for (int i = 0; i < 4; i++) {
            const int qg = qt * 64 + ty * 4 + i;
            #pragma unroll
            for (int j = 0; j < 2; j++) {
                const int kg = kt * 32 + tx * 2 + j;
                Ss[ty * 4 + i][tx * 2 + j] =
                    (kg > qg) ? -1e5f : sv[i][j] * 0.125f;
            }
        }
        __syncthreads();

        // online softmax update: one thread per query row
        if (tid < 64) {
            const int r = tid;
            float rowmax = -1e30f;
            #pragma unroll
            for (int c = 0; c < 32; c++) rowmax = fmaxf(rowmax, Ss[r][c]);
            const float newm = fmaxf(m_r, rowmax);
            const float al   = __expf(m_r - newm);
            float sum = 0.f;
            #pragma unroll
            for (int c = 0; c < 32; c++) {
                float p = __expf(Ss[r][c] - newm);
                Ss[r][c] = p;
                sum += p;
            }
            l_r = l_r * al + sum;
            m_r = newm;
            alpha_s[r] = al;
        }
        __syncthreads();

        // rescale accumulator + O += P V
        float al[4];
        #pragma unroll
        for (int i = 0; i < 4; i++) al[i] = alpha_s[ty * 4 + i];
        #pragma unroll
        for (int i = 0; i < 4; i++)
            #pragma unroll
            for (int j = 0; j < 4; j++) acc[i][j] *= al[i];

        #pragma unroll
        for (int kk = 0; kk < 32; kk++) {
            float4 vr = *reinterpret_cast<const float4*>(&Vs[kk][tx * 4]);
            #pragma unroll
            for (int i = 0; i < 4; i++) {
                const float p = Ss[ty * 4 + i][kk];
                acc[i][0] += p * vr.x;
                acc[i][1] += p * vr.y;
                acc[i][2] += p * vr.z;
                acc[i][3] += p * vr.w;
            }
        }
    }

    if (tid < 64) l_s[tid] = l_r;
    __syncthreads();

    float* zbase = g_z + ((size_t)b * 2048 + (size_t)qt * 64) * 1024 + head_off;
    #pragma unroll
    for (int i = 0; i < 4; i++) {
        const int row = ty * 4 + i;
        const float inv = 1.0f / l_s[row];
        float4 o;
        o.x = acc[i][0] * inv;
        o.y = acc[i][1] * inv;
        o.z = acc[i][2] * inv;
        o.w = acc[i][3] * inv;
        *reinterpret_cast<float4*>(zbase + (size_t)row * 1024 + tx * 4) = o;
    }
}

// ---------------------------------------------------------------------------
// Stage 3: output projection.  out = z (8192x1024) @ W_O(flat 1024x1024) + b_O
// (W_O[n][h][e] flattened is exactly row-major [n*64+h][e].)
// ---------------------------------------------------------------------------
__global__ __launch_bounds__(256) void out_gemm(
    const float* __restrict__ WO, const float* __restrict__ bO,
    float* __restrict__ out)
{
    __shared__ float As[16][64];
    __shared__ float Bs[16][64];

    const int bm  = blockIdx.y * 64;
    const int bn  = blockIdx.x * 64;
    const int tid = threadIdx.x;
    const int tx  = tid & 15;
    const int ty  = tid >> 4;

    float acc[4][4] = {};

    for (int k0 = 0; k0 < 1024; k0 += 16) {
        {
            int row = tid >> 2;
            int col = (tid & 3) * 4;
            float4 va = *reinterpret_cast<const float4*>(
                g_z + (size_t)(bm + row) * 1024 + k0 + col);
            As[col + 0][row] = va.x;
            As[col + 1][row] = va.y;
            As[col + 2][row] = va.z;
            As[col + 3][row] = va.w;
            int kr = tid >> 4;
            int nc = (tid & 15) * 4;
            *reinterpret_cast<float4*>(&Bs[kr][nc]) =
                *reinterpret_cast<const float4*>(WO + (size_t)(k0 + kr) * 1024 + bn + nc);
        }
        __syncthreads();

        #pragma unroll
        for (int kk = 0; kk < 16; kk++) {
            float4 a = *reinterpret_cast<const float4*>(&As[kk][ty * 4]);
            float4 b = *reinterpret_cast<const float4*>(&Bs[kk][tx * 4]);
            float av[4] = {a.x, a.y, a.z, a.w};
            float bv[4] = {b.x, b.y, b.z, b.w};
            #pragma unroll
            for (int i = 0; i < 4; i++)
                #pragma unroll
                for (int j = 0; j < 4; j++)
                    acc[i][j] += av[i] * bv[j];
        }
        __syncthreads();
    }

    #pragma unroll
    for (int i = 0; i < 4; i++) {
        const int r = bm + ty * 4 + i;
        #pragma unroll
        for (int j = 0; j < 4; j++) {
            const int c = bn + tx * 4 + j;
            out[(size_t)r * 1024 + c] = acc[i][j] + bO[c];
        }
    }
}

// ---------------------------------------------------------------------------
extern "C" void kernel_launch(void* const* d_in, const int* in_sizes, int n_in,
                              void* d_out, int out_size)
{
    (void)in_sizes; (void)n_in; (void)out_size;
    const float* x  = (const float*)d_in[0];
    const float* WQ = (const float*)d_in[1];
    const float* bQ = (const float*)d_in[2];
    const float* WK = (const float*)d_in[3];
    const float* bK = (const float*)d_in[4];
    const float* WV = (const float*)d_in[5];
    const float* bV = (const float*)d_in[6];
    const float* WO = (const float*)d_in[7];
    const float* bO = (const float*)d_in[8];
    float* out = (float*)d_out;

    // Stage 1: QKV projections (z-dim selects Q/K/V)
    {
        dim3 grid(1024 / 64, BSROWS / 64, 3);
        qkv_gemm<<<grid, 256>>>(x, WQ, bQ, WK, bK, WV, bV);
    }
    // Stage 2: attention
    {
        dim3 grid(2048 / 64, 4 * 16);
        attn_kernel<<<grid, 256>>>();
    }
    // Stage 3: output projection
    {
        dim3 grid(1024 / 64, BSROWS / 64);
        out_gemm<<<grid, 256>>>(WO, bO, out);
    }
}

// round 4
// speedup vs baseline: 2.9552x; 2.9552x over previous
#include <cuda_runtime.h>
#include <cuda_bf16.h>

// ---------------------------------------------------------------------------
// Attention_9947144257674 — round 4: mma.sync bf16 split-precision everywhere.
//   Fix vs round 3: wsplit stored the W_O slice untransposed ([k][n] instead of
//   the [n][k] the gemm B-operand needs) -> O-projection used W^T. One-line fix.
// ---------------------------------------------------------------------------

#define BSROWS 8192
#define DM     1024

// bf16 hi/lo operands
__device__ __nv_bfloat16 g_xhi[(size_t)BSROWS * DM];
__device__ __nv_bfloat16 g_xlo[(size_t)BSROWS * DM];
__device__ __nv_bfloat16 g_wthi[(size_t)4 * DM * DM];  // [slice][c][e], 0=Q,1=K,2=V,3=O
__device__ __nv_bfloat16 g_wtlo[(size_t)4 * DM * DM];
__device__ __nv_bfloat16 g_qhi[(size_t)BSROWS * DM];
__device__ __nv_bfloat16 g_qlo[(size_t)BSROWS * DM];
__device__ __nv_bfloat16 g_khi[(size_t)BSROWS * DM];
__device__ __nv_bfloat16 g_klo[(size_t)BSROWS * DM];
__device__ __nv_bfloat16 g_vhi[(size_t)BSROWS * DM];
__device__ __nv_bfloat16 g_vlo[(size_t)BSROWS * DM];
__device__ __nv_bfloat16 g_vthi[(size_t)64 * 64 * 2048];  // [b*16+h][d][s]
__device__ __nv_bfloat16 g_vtlo[(size_t)64 * 64 * 2048];
__device__ __nv_bfloat16 g_zhi[(size_t)BSROWS * DM];
__device__ __nv_bfloat16 g_zlo[(size_t)BSROWS * DM];

// ---------------------------------------------------------------------------
// helpers
// ---------------------------------------------------------------------------
__device__ __forceinline__ unsigned smem_u32(const void* p) {
    unsigned a;
    asm("{ .reg .u64 t; cvta.to.shared.u64 t, %1; cvt.u32.u64 %0, t; }"
        : "=r"(a) : "l"(p));
    return a;
}

__device__ __forceinline__ void ldmx4(unsigned addr, unsigned& r0, unsigned& r1,
                                      unsigned& r2, unsigned& r3) {
    asm volatile("ldmatrix.sync.aligned.m8n8.x4.shared.b16 {%0,%1,%2,%3}, [%4];"
                 : "=r"(r0), "=r"(r1), "=r"(r2), "=r"(r3) : "r"(addr));
}

__device__ __forceinline__ void mmabf16(float* c, const unsigned* a,
                                        unsigned b0, unsigned b1) {
    asm volatile(
        "mma.sync.aligned.m16n8k16.row.col.f32.bf16.bf16.f32 "
        "{%0,%1,%2,%3}, {%4,%5,%6,%7}, {%8,%9}, {%0,%1,%2,%3};"
        : "+f"(c[0]), "+f"(c[1]), "+f"(c[2]), "+f"(c[3])
        : "r"(a[0]), "r"(a[1]), "r"(a[2]), "r"(a[3]), "r"(b0), "r"(b1));
}

#define CPASYNC16(sa, g) \
    asm volatile("cp.async.cg.shared.global [%0], [%1], 16;" :: "r"(sa), "l"(g) : "memory")
#define CPCOMMIT() asm volatile("cp.async.commit_group;" ::: "memory")
#define CPWAIT0()  asm volatile("cp.async.wait_group 0;" ::: "memory")
#define CPWAIT1()  asm volatile("cp.async.wait_group 1;" ::: "memory")

__device__ __forceinline__ unsigned pack_bf2(float v0, float v1) {
    __nv_bfloat162 t;
    t.x = __float2bfloat16(v0);
    t.y = __float2bfloat16(v1);
    return *reinterpret_cast<unsigned*>(&t);
}

// ---------------------------------------------------------------------------
// fp32 -> bf16 hi/lo split
// ---------------------------------------------------------------------------
__global__ __launch_bounds__(256) void fsplit(const float* __restrict__ src,
                                              __nv_bfloat16* __restrict__ hi,
                                              __nv_bfloat16* __restrict__ lo) {
    size_t i = ((size_t)blockIdx.x * 256 + threadIdx.x) * 4;
    float4 v = *reinterpret_cast<const float4*>(src + i);
    float vv[4] = {v.x, v.y, v.z, v.w};
    __nv_bfloat162 H0, H1, L0, L1;
    __nv_bfloat16 h0 = __float2bfloat16(vv[0]);
    __nv_bfloat16 h1 = __float2bfloat16(vv[1]);
    __nv_bfloat16 h2 = __float2bfloat16(vv[2]);
    __nv_bfloat16 h3 = __float2bfloat16(vv[3]);
    H0.x = h0; H0.y = h1; H1.x = h2; H1.y = h3;
    L0.x = __float2bfloat16(vv[0] - __bfloat162float(h0));
    L0.y = __float2bfloat16(vv[1] - __bfloat162float(h1));
    L1.x = __float2bfloat16(vv[2] - __bfloat162float(h2));
    L1.y = __float2bfloat16(vv[3] - __bfloat162float(h3));
    *reinterpret_cast<__nv_bfloat162*>(hi + i)     = H0;
    *reinterpret_cast<__nv_bfloat162*>(hi + i + 2) = H1;
    *reinterpret_cast<__nv_bfloat162*>(lo + i)     = L0;
    *reinterpret_cast<__nv_bfloat162*>(lo + i + 2) = L1;
}

// ---------------------------------------------------------------------------
// weight transpose + split: Bt[c][e], c = gemm output column, e = k index
//   QKV (m<3): out col c=n*64+h, k=e     -> src = W[(c>>6)*65536 + e*64 + (c&63)]
//   O   (m=3): out col c=e_model, k=c_in -> src = WO_flat[e(k)*1024... i.e.
//              Bt[c][e] = WO_flat[e][c]  -> src = e*1024 + c   (ROUND-4 FIX)
// ---------------------------------------------------------------------------
__global__ __launch_bounds__(256) void wsplit(const float* __restrict__ WQ,
                                              const float* __restrict__ WK,
                                              const float* __restrict__ WV,
                                              const float* __restrict__ WO) {
    const int m = blockIdx.z;
    const float* W = (m == 0) ? WQ : (m == 1) ? WK : (m == 2) ? WV : WO;
    __nv_bfloat16* DH = g_wthi + (size_t)m * DM * DM;
    __nv_bfloat16* DL = g_wtlo + (size_t)m * DM * DM;

    __shared__ float t[32][33];
    const int c0 = blockIdx.x * 32, e0 = blockIdx.y * 32;
    const int tx = threadIdx.x, ty = threadIdx.y;   // 32 x 8

    #pragma unroll
    for (int j = 0; j < 4; j++) {
        int c = c0 + tx, e = e0 + ty + j * 8;
        size_t src = (m < 3)
            ? ((size_t)(c >> 6) * 65536 + (size_t)e * 64 + (c & 63))
            : ((size_t)e * 1024 + c);                        // FIX: WO transposed
        t[tx][ty + j * 8] = W[src];
    }
    __syncthreads();
    #pragma unroll
    for (int j = 0; j < 4; j++) {
        int e = e0 + tx, c = c0 + ty + j * 8;
        float v = t[ty + j * 8][tx];
        __nv_bfloat16 h = __float2bfloat16(v);
        DH[(size_t)c * 1024 + e] = h;
        DL[(size_t)c * 1024 + e] = __float2bfloat16(v - __bfloat162float(h));
    }
}

// ---------------------------------------------------------------------------
// V transpose: vhi/vlo [b*2048+s][h*64+d] -> vt [b*16+h][d][s]
// ---------------------------------------------------------------------------
__global__ void vtrans() {
    __shared__ __nv_bfloat16 th[32][34];
    __shared__ __nv_bfloat16 tl[32][34];
    const int b  = blockIdx.z;
    const int s0 = blockIdx.x * 32;
    const int c0 = blockIdx.y * 32;
    const int tx = threadIdx.x, ty = threadIdx.y;   // 32 x 8

    #pragma unroll
    for (int j = 0; j < 4; j++) {
        int s = s0 + ty + j * 8, c = c0 + tx;
        size_t idx = ((size_t)b * 2048 + s) * DM + c;
        th[ty + j * 8][tx] = g_vhi[idx];
        tl[ty + j * 8][tx] = g_vlo[idx];
    }
    __syncthreads();
    #pragma unroll
    for (int j = 0; j < 4; j++) {
        int c = c0 + ty + j * 8, s = s0 + tx;
        size_t o = ((size_t)(b * 16 + (c >> 6)) * 64 + (c & 63)) * 2048 + s;
        g_vthi[o] = th[tx][ty + j * 8];
        g_vtlo[o] = tl[tx][ty + j * 8];
    }
}

// ---------------------------------------------------------------------------
// mma GEMM: C[m][c] = sum_e A[m][e]*Bt[c][e] (+bias), split-precision 3-pass.
// 128x128 tile, 8 warps (4m x 2n), K-chunk 32 bf16, double-buffered cp.async.
// ---------------------------------------------------------------------------
#define GS       80
#define GARR     10240           // 128*80
#define GBUF     40960           // 4 arrays
#define SMEM_G   81920

__global__ __launch_bounds__(256) void gemm_mma(
    const __nv_bfloat16* __restrict__ Ahi, const __nv_bfloat16* __restrict__ Alo,
    const float* __restrict__ bQ, const float* __restrict__ bK,
    const float* __restrict__ bV, float* __restrict__ out_f32, int o_mode)
{
    extern __shared__ __align__(128) char sm[];
    const int tid  = threadIdx.x;
    const int lane = tid & 31, w = tid >> 5;
    const int wm = w >> 1, wn = w & 1;
    const int z  = blockIdx.z;
    const int bm = blockIdx.y * 128, bn = blockIdx.x * 128;

    const int slice = o_mode ? 3 : z;
    const __nv_bfloat16* Bh = g_wthi + (size_t)slice * DM * DM + (size_t)bn * DM;
    const __nv_bfloat16* Bl = g_wtlo + (size_t)slice * DM * DM + (size_t)bn * DM;
    const __nv_bfloat16* Ah = Ahi + (size_t)bm * DM;
    const __nv_bfloat16* Al = Alo + (size_t)bm * DM;
    const float* bias = o_mode ? bQ : (z == 0 ? bQ : (z == 1 ? bK : bV));
    __nv_bfloat16* Ohi = (z == 0) ? g_qhi : (z == 1) ? g_khi : g_vhi;
    __nv_bfloat16* Olo = (z == 0) ? g_qlo : (z == 1) ? g_klo : g_vlo;

    const unsigned sbase = smem_u32(sm);

    float acc[2][8][4];
    #pragma unroll
    for (int i = 0; i < 2; i++)
        #pragma unroll
        for (int j = 0; j < 8; j++)
            #pragma unroll
            for (int e = 0; e < 4; e++) acc[i][j][e] = 0.f;

    const __nv_bfloat16* srcs[4] = {Ah, Al, Bh, Bl};

    auto fill = [&](int buf, int k0) {
        #pragma unroll
        for (int a = 0; a < 4; a++) {
            unsigned ab = sbase + buf * GBUF + a * GARR;
            #pragma unroll
            for (int i = 0; i < 2; i++) {
                int c = tid + i * 256;
                int row = c >> 2, q = c & 3;
                unsigned sa = ab + row * GS + q * 16;
                CPASYNC16(sa, srcs[a] + (size_t)row * DM + k0 + q * 8);
            }
        }
        CPCOMMIT();
    };

    fill(0, 0);
    #pragma unroll 1
    for (int ci = 0; ci < 32; ci++) {
        const int buf = ci & 1;
        if (ci + 1 < 32) { fill(buf ^ 1, (ci + 1) * 32); CPWAIT1(); }
        else             { CPWAIT0(); }
        __syncthreads();

        const unsigned Ab = sbase + buf * GBUF;
        const unsigned Bb = Ab + 2 * GARR;
        #pragma unroll
        for (int ks = 0; ks < 2; ks++) {
            const int kb = ks * 32;
            unsigned ah[2][4], al[2][4];
            #pragma unroll
            for (int i = 0; i < 2; i++) {
                unsigned aaddr = Ab + (wm * 32 + i * 16 + (lane & 15)) * GS + kb
                                 + ((lane >> 4) & 1) * 16;
                ldmx4(aaddr, ah[i][0], ah[i][1], ah[i][2], ah[i][3]);
                ldmx4(aaddr + GARR, al[i][0], al[i][1], al[i][2], al[i][3]);
            }
            #pragma unroll
            for (int jj = 0; jj < 4; jj++) {
                unsigned baddr = Bb + (wn * 64 + jj * 16 + (lane & 7)
                                 + ((lane >> 4) & 1) * 8) * GS + kb
                                 + ((lane >> 3) & 1) * 16;
                unsigned bh0, bh1, bh2, bh3, bl0, bl1, bl2, bl3;
                ldmx4(baddr, bh0, bh1, bh2, bh3);
                ldmx4(baddr + GARR, bl0, bl1, bl2, bl3);
                #pragma unroll
                for (int i = 0; i < 2; i++) {
                    mmabf16(acc[i][jj * 2],     ah[i], bh0, bh1);
                    mmabf16(acc[i][jj * 2],     al[i], bh0, bh1);
                    mmabf16(acc[i][jj * 2],     ah[i], bl0, bl1);
                    mmabf16(acc[i][jj * 2 + 1], ah[i], bh2, bh3);
                    mmabf16(acc[i][jj * 2 + 1], al[i], bh2, bh3);
                    mmabf16(acc[i][jj * 2 + 1], ah[i], bl2, bl3);
                }
            }
        }
        __syncthreads();
    }

    // epilogue
    #pragma unroll
    for (int i = 0; i < 2; i++) {
        const int row = bm + wm * 32 + i * 16 + (lane >> 2);
        #pragma unroll
        for (int j = 0; j < 8; j++) {
            const int col = bn + wn * 64 + j * 8 + (lane & 3) * 2;
            float v0 = acc[i][j][0] + bias[col];
            float v1 = acc[i][j][1] + bias[col + 1];
            float v2 = acc[i][j][2] + bias[col];
            float v3 = acc[i][j][3] + bias[col + 1];
            if (o_mode) {
                float2 a = {v0, v1}, b2 = {v2, v3};
                *reinterpret_cast<float2*>(&out_f32[(size_t)row * DM + col]) = a;
                *reinterpret_cast<float2*>(&out_f32[(size_t)(row + 8) * DM + col]) = b2;
            } else {
                __nv_bfloat162 h2, l2;
                h2.x = __float2bfloat16(v0); h2.y = __float2bfloat16(v1);
                l2.x = __float2bfloat16(v0 - __bfloat162float(h2.x));
                l2.y = __float2bfloat16(v1 - __bfloat162float(h2.y));
                *reinterpret_cast<__nv_bfloat162*>(&Ohi[(size_t)row * DM + col]) = h2;
                *reinterpret_cast<__nv_bfloat162*>(&Olo[(size_t)row * DM + col]) = l2;
                h2.x = __float2bfloat16(v2); h2.y = __float2bfloat16(v3);
                l2.x = __float2bfloat16(v2 - __bfloat162float(h2.x));
                l2.y = __float2bfloat16(v3 - __bfloat162float(h2.y));
                *reinterpret_cast<__nv_bfloat162*>(&Ohi[(size_t)(row + 8) * DM + col]) = h2;
                *reinterpret_cast<__nv_bfloat162*>(&Olo[(size_t)(row + 8) * DM + col]) = l2;
            }
        }
    }
}

// ---------------------------------------------------------------------------
// flash attention on mma.sync, split-precision for QK^T and PV.
// block 128 (4 warps, 16 q-rows each), 64 q-rows/CTA, key tiles of 64.
// ---------------------------------------------------------------------------
#define AS      144
#define AARR    9216            // 64*144
#define SMEM_A  55296

__global__ __launch_bounds__(128) void attn_mma()
{
    extern __shared__ __align__(128) char sm[];
    const int tid = threadIdx.x, lane = tid & 31, w = tid >> 5;
    const int qt = (int)gridDim.x - 1 - (int)blockIdx.x;   // big tiles first
    const int bh = blockIdx.y;
    const int b = bh >> 4, h = bh & 15;

    const unsigned sb = smem_u32(sm);
    const unsigned Qh = sb, Kh = sb + 2 * AARR, Vh = sb + 4 * AARR;

    const size_t qrow0 = (size_t)b * 2048 + (size_t)qt * 64;
    const size_t hoff  = (size_t)h * 64;

    {
        const __nv_bfloat16* qh = g_qhi + qrow0 * DM + hoff;
        const __nv_bfloat16* ql = g_qlo + qrow0 * DM + hoff;
        #pragma unroll
        for (int i = 0; i < 4; i++) {
            int c = tid + i * 128;
            int row = c >> 3, q = c & 7;
            unsigned sa = Qh + row * AS + q * 16;
            CPASYNC16(sa,        qh + (size_t)row * DM + q * 8);
            CPASYNC16(sa + AARR, ql + (size_t)row * DM + q * 8);
        }
        CPCOMMIT(); CPWAIT0();
        __syncthreads();
    }
    unsigned qfh[4][4], qfl[4][4];
    #pragma unroll
    for (int ks = 0; ks < 4; ks++) {
        unsigned aaddr = Qh + (w * 16 + (lane & 15)) * AS + ks * 32
                         + ((lane >> 4) & 1) * 16;
        ldmx4(aaddr, qfh[ks][0], qfh[ks][1], qfh[ks][2], qfh[ks][3]);
        ldmx4(aaddr + AARR, qfl[ks][0], qfl[ks][1], qfl[ks][2], qfl[ks][3]);
    }

    float o[8][4];
    #pragma unroll
    for (int j = 0; j < 8; j++)
        #pragma unroll
        for (int e = 0; e < 4; e++) o[j][e] = 0.f;
    float m0 = -1e30f, m1 = -1e30f, l0 = 0.f, l1 = 0.f;

    const __nv_bfloat16* kh = g_khi + (size_t)b * 2048 * DM + hoff;
    const __nv_bfloat16* kl = g_klo + (size_t)b * 2048 * DM + hoff;
    const __nv_bfloat16* vh = g_vthi + (size_t)bh * 64 * 2048;
    const __nv_bfloat16* vl = g_vtlo + (size_t)bh * 64 * 2048;

    #pragma unroll 1
    for (int kt = 0; kt <= qt; kt++) {
        __syncthreads();
        #pragma unroll
        for (int i = 0; i < 4; i++) {
            int c = tid + i * 128;
            int row = c >> 3, q = c & 7;
            unsigned ksa = Kh + row * AS + q * 16;
            unsigned vsa = Vh + row * AS + q * 16;
            CPASYNC16(ksa,        kh + (size_t)(kt * 64 + row) * DM + q * 8);
            CPASYNC16(ksa + AARR, kl + (size_t)(kt * 64 + row) * DM + q * 8);
            CPASYNC16(vsa,        vh + (size_t)row * 2048 + kt * 64 + q * 8);
            CPASYNC16(vsa + AARR, vl + (size_t)row * 2048 + kt * 64 + q * 8);
        }
        CPCOMMIT(); CPWAIT0();
        __syncthreads();

        // ---- S = Q K^T (3-split) ----
        float s[8][4];
        #pragma unroll
        for (int j = 0; j < 8; j++)
            #pragma unroll
            for (int e = 0; e < 4; e++) s[j][e] = 0.f;

        #pragma unroll
        for (int ks = 0; ks < 4; ks++) {
            const int kb = ks * 32;
            #pragma unroll
            for (int jj = 0; jj < 4; jj++) {
                unsigned baddr = Kh + (jj * 16 + (lane & 7) + ((lane >> 4) & 1) * 8) * AS
                                 + kb + ((lane >> 3) & 1) * 16;
                unsigned b0, b1, b2, b3, c0, c1, c2, c3;
                ldmx4(baddr, b0, b1, b2, b3);
                ldmx4(baddr + AARR, c0, c1, c2, c3);
                mmabf16(s[jj * 2],     qfh[ks], b0, b1);
                mmabf16(s[jj * 2],     qfl[ks], b0, b1);
                mmabf16(s[jj * 2],     qfh[ks], c0, c1);
                mmabf16(s[jj * 2 + 1], qfh[ks], b2, b3);
                mmabf16(s[jj * 2 + 1], qfl[ks], b2, b3);
                mmabf16(s[jj * 2 + 1], qfh[ks], c2, c3);
            }
        }

        // ---- scale + causal mask + online softmax ----
        #pragma unroll
        for (int j = 0; j < 8; j++)
            #pragma unroll
            for (int e = 0; e < 4; e++) s[j][e] *= 0.125f;

        const int r0 = w * 16 + (lane >> 2), r1 = r0 + 8;
        if (kt == qt) {
            #pragma unroll
            for (int j = 0; j < 8; j++) {
                const int cb = j * 8 + (lane & 3) * 2;
                if (cb     > r0) s[j][0] = -1e5f;
                if (cb + 1 > r0) s[j][1] = -1e5f;
                if (cb     > r1) s[j][2] = -1e5f;
                if (cb + 1 > r1) s[j][3] = -1e5f;
            }
        }
        float mx0 = -1e30f, mx1 = -1e30f;
        #pragma unroll
        for (int j = 0; j < 8; j++) {
            mx0 = fmaxf(mx0, fmaxf(s[j][0], s[j][1]));
            mx1 = fmaxf(mx1, fmaxf(s[j][2], s[j][3]));
        }
        mx0 = fmaxf(mx0, __shfl_xor_sync(0xffffffffu, mx0, 1));
        mx0 = fmaxf(mx0, __shfl_xor_sync(0xffffffffu, mx0, 2));
        mx1 = fmaxf(mx1, __shfl_xor_sync(0xffffffffu, mx1, 1));
        mx1 = fmaxf(mx1, __shfl_xor_sync(0xffffffffu, mx1, 2));
        const float nm0 = fmaxf(m0, mx0), nm1 = fmaxf(m1, mx1);
        const float a0 = __expf(m0 - nm0), a1 = __expf(m1 - nm1);
        m0 = nm0; m1 = nm1;
        float sum0 = 0.f, sum1 = 0.f;
        #pragma unroll
        for (int j = 0; j < 8; j++) {
            s[j][0] = __expf(s[j][0] - nm0); sum0 += s[j][0];
            s[j][1] = __expf(s[j][1] - nm0); sum0 += s[j][1];
            s[j][2] = __expf(s[j][2] - nm1); sum1 += s[j][2];
            s[j][3] = __expf(s[j][3] - nm1); sum1 += s[j][3];
        }
        sum0 += __shfl_xor_sync(0xffffffffu, sum0, 1);
        sum0 += __shfl_xor_sync(0xffffffffu, sum0, 2);
        sum1 += __shfl_xor_sync(0xffffffffu, sum1, 1);
        sum1 += __shfl_xor_sync(0xffffffffu, sum1, 2);
        l0 = l0 * a0 + sum0;
        l1 = l1 * a1 + sum1;
        #pragma unroll
        for (int j = 0; j < 8; j++) {
            o[j][0] *= a0; o[j][1] *= a0; o[j][2] *= a1; o[j][3] *= a1;
        }

        // ---- O += P V (3-split) ----
        #pragma unroll
        for (int kk = 0; kk < 4; kk++) {
            const int t0 = kk * 2, t1 = kk * 2 + 1;
            unsigned pah[4], pal[4];
            {
                float v0 = s[t0][0], v1 = s[t0][1];
                pah[0] = pack_bf2(v0, v1);
                pal[0] = pack_bf2(v0 - __bfloat162float(__float2bfloat16(v0)),
                                  v1 - __bfloat162float(__float2bfloat16(v1)));
                v0 = s[t0][2]; v1 = s[t0][3];
                pah[1] = pack_bf2(v0, v1);
                pal[1] = pack_bf2(v0 - __bfloat162float(__float2bfloat16(v0)),
                                  v1 - __bfloat162float(__float2bfloat16(v1)));
                v0 = s[t1][0]; v1 = s[t1][1];
                pah[2] = pack_bf2(v0, v1);
                pal[2] = pack_bf2(v0 - __bfloat162float(__float2bfloat16(v0)),
                                  v1 - __bfloat162float(__float2bfloat16(v1)));
                v0 = s[t1][2]; v1 = s[t1][3];
                pah[3] = pack_bf2(v0, v1);
                pal[3] = pack_bf2(v0 - __bfloat162float(__float2bfloat16(v0)),
                                  v1 - __bfloat162float(__float2bfloat16(v1)));
            }
            #pragma unroll
            for (int jj = 0; jj < 4; jj++) {
                unsigned baddr = Vh + (jj * 16 + (lane & 7) + ((lane >> 4) & 1) * 8) * AS
                                 + kk * 32 + ((lane >> 3) & 1) * 16;
                unsigned b0, b1, b2, b3, c0, c1, c2, c3;
                ldmx4(baddr, b0, b1, b2, b3);
                ldmx4(baddr + AARR, c0, c1, c2, c3);
                mmabf16(o[jj * 2],     pah, b0, b1);
                mmabf16(o[jj * 2],     pal, b0, b1);
                mmabf16(o[jj * 2],     pah, c0, c1);
                mmabf16(o[jj * 2 + 1], pah, b2, b3);
                mmabf16(o[jj * 2 + 1], pal, b2, b3);
                mmabf16(o[jj * 2 + 1], pah, c2, c3);
            }
        }
    }

    // ---- finalize + write z (bf16 hi/lo) ----
    const float inv0 = 1.0f / l0, inv1 = 1.0f / l1;
    const size_t row0 = qrow0 + w * 16 + (lane >> 2);
    #pragma unroll
    for (int j = 0; j < 8; j++) {
        const size_t col = hoff + j * 8 + (lane & 3) * 2;
        float v0 = o[j][0] * inv0, v1 = o[j][1] * inv0;
        float v2 = o[j][2] * inv1, v3 = o[j][3] * inv1;
        __nv_bfloat162 h2, l2;
        h2.x = __float2bfloat16(v0); h2.y = __float2bfloat16(v1);
        l2.x = __float2bfloat16(v0 - __bfloat162float(h2.x));
        l2.y = __float2bfloat16(v1 - __bfloat162float(h2.y));
        *reinterpret_cast<__nv_bfloat162*>(&g_zhi[row0 * DM + col]) = h2;
        *reinterpret_cast<__nv_bfloat162*>(&g_zlo[row0 * DM + col]) = l2;
        h2.x = __float2bfloat16(v2); h2.y = __float2bfloat16(v3);
        l2.x = __float2bfloat16(v2 - __bfloat162float(h2.x));
        l2.y = __float2bfloat16(v3 - __bfloat162float(h2.y));
        *reinterpret_cast<__nv_bfloat162*>(&g_zhi[(row0 + 8) * DM + col]) = h2;
        *reinterpret_cast<__nv_bfloat162*>(&g_zlo[(row0 + 8) * DM + col]) = l2;
    }
}

// ---------------------------------------------------------------------------
extern "C" void kernel_launch(void* const* d_in, const int* in_sizes, int n_in,
                              void* d_out, int out_size)
{
    (void)in_sizes; (void)n_in; (void)out_size;
    const float* x  = (const float*)d_in[0];
    const float* WQ = (const float*)d_in[1];
    const float* bQ = (const float*)d_in[2];
    const float* WK = (const float*)d_in[3];
    const float* bK = (const float*)d_in[4];
    const float* WV = (const float*)d_in[5];
    const float* bV = (const float*)d_in[6];
    const float* WO = (const float*)d_in[7];
    const float* bO = (const float*)d_in[8];
    float* out = (float*)d_out;

    cudaFuncSetAttribute(gemm_mma, cudaFuncAttributeMaxDynamicSharedMemorySize, SMEM_G);
    cudaFuncSetAttribute(attn_mma, cudaFuncAttributeMaxDynamicSharedMemorySize, SMEM_A);

    __nv_bfloat16 *xhi, *xlo, *zhi, *zlo;
    cudaGetSymbolAddress((void**)&xhi, g_xhi);
    cudaGetSymbolAddress((void**)&xlo, g_xlo);
    cudaGetSymbolAddress((void**)&zhi, g_zhi);
    cudaGetSymbolAddress((void**)&zlo, g_zlo);

    // prep
    fsplit<<<(BSROWS * DM) / 1024, 256>>>(x, xhi, xlo);
    wsplit<<<dim3(32, 32, 4), dim3(32, 8)>>>(WQ, WK, WV, WO);

    // QKV projections (write q/k/v bf16 hi/lo directly)
    gemm_mma<<<dim3(8, 64, 3), 256, SMEM_G>>>(xhi, xlo, bQ, bK, bV, nullptr, 0);

    // V transpose for PV mma operand
    vtrans<<<dim3(64, 32, 4), dim3(32, 8)>>>();

    // attention
    attn_mma<<<dim3(32, 64), 128, SMEM_A>>>();

    // O projection
    gemm_mma<<<dim3(8, 64, 1), 256, SMEM_G>>>(zhi, zlo, bO, bO, bO, out, 1);
}

// round 5
// speedup vs baseline: 3.1973x; 1.0819x over previous
#include <cuda_runtime.h>
#include <cuda_bf16.h>

// ---------------------------------------------------------------------------
// Attention_9947144257674 — round 5: scheduling fixes.
//   - attn: BQ=128, double-buffered K/V tiles, 2 CTAs/SM
//   - gemm: 2 CTAs/SM via __launch_bounds__(256, 2)
//   Numerics identical to round 4 (3-pass bf16 split everywhere).
// ---------------------------------------------------------------------------

#define BSROWS 8192
#define DM     1024

__device__ __nv_bfloat16 g_xhi[(size_t)BSROWS * DM];
__device__ __nv_bfloat16 g_xlo[(size_t)BSROWS * DM];
__device__ __nv_bfloat16 g_wthi[(size_t)4 * DM * DM];  // [slice][c][e]
__device__ __nv_bfloat16 g_wtlo[(size_t)4 * DM * DM];
__device__ __nv_bfloat16 g_qhi[(size_t)BSROWS * DM];
__device__ __nv_bfloat16 g_qlo[(size_t)BSROWS * DM];
__device__ __nv_bfloat16 g_khi[(size_t)BSROWS * DM];
__device__ __nv_bfloat16 g_klo[(size_t)BSROWS * DM];
__device__ __nv_bfloat16 g_vhi[(size_t)BSROWS * DM];
__device__ __nv_bfloat16 g_vlo[(size_t)BSROWS * DM];
__device__ __nv_bfloat16 g_vthi[(size_t)64 * 64 * 2048];  // [b*16+h][d][s]
__device__ __nv_bfloat16 g_vtlo[(size_t)64 * 64 * 2048];
__device__ __nv_bfloat16 g_zhi[(size_t)BSROWS * DM];
__device__ __nv_bfloat16 g_zlo[(size_t)BSROWS * DM];

// ---------------------------------------------------------------------------
__device__ __forceinline__ unsigned smem_u32(const void* p) {
    unsigned a;
    asm("{ .reg .u64 t; cvta.to.shared.u64 t, %1; cvt.u32.u64 %0, t; }"
        : "=r"(a) : "l"(p));
    return a;
}

__device__ __forceinline__ void ldmx4(unsigned addr, unsigned& r0, unsigned& r1,
                                      unsigned& r2, unsigned& r3) {
    asm volatile("ldmatrix.sync.aligned.m8n8.x4.shared.b16 {%0,%1,%2,%3}, [%4];"
                 : "=r"(r0), "=r"(r1), "=r"(r2), "=r"(r3) : "r"(addr));
}

__device__ __forceinline__ void mmabf16(float* c, const unsigned* a,
                                        unsigned b0, unsigned b1) {
    asm volatile(
        "mma.sync.aligned.m16n8k16.row.col.f32.bf16.bf16.f32 "
        "{%0,%1,%2,%3}, {%4,%5,%6,%7}, {%8,%9}, {%0,%1,%2,%3};"
        : "+f"(c[0]), "+f"(c[1]), "+f"(c[2]), "+f"(c[3])
        : "r"(a[0]), "r"(a[1]), "r"(a[2]), "r"(a[3]), "r"(b0), "r"(b1));
}

#define CPASYNC16(sa, g) \
    asm volatile("cp.async.cg.shared.global [%0], [%1], 16;" :: "r"(sa), "l"(g) : "memory")
#define CPCOMMIT() asm volatile("cp.async.commit_group;" ::: "memory")
#define CPWAIT0()  asm volatile("cp.async.wait_group 0;" ::: "memory")
#define CPWAIT1()  asm volatile("cp.async.wait_group 1;" ::: "memory")

__device__ __forceinline__ unsigned pack_bf2(float v0, float v1) {
    __nv_bfloat162 t;
    t.x = __float2bfloat16(v0);
    t.y = __float2bfloat16(v1);
    return *reinterpret_cast<unsigned*>(&t);
}

// ---------------------------------------------------------------------------
__global__ __launch_bounds__(256) void fsplit(const float* __restrict__ src,
                                              __nv_bfloat16* __restrict__ hi,
                                              __nv_bfloat16* __restrict__ lo) {
    size_t i = ((size_t)blockIdx.x * 256 + threadIdx.x) * 4;
    float4 v = *reinterpret_cast<const float4*>(src + i);
    float vv[4] = {v.x, v.y, v.z, v.w};
    __nv_bfloat162 H0, H1, L0, L1;
    __nv_bfloat16 h0 = __float2bfloat16(vv[0]);
    __nv_bfloat16 h1 = __float2bfloat16(vv[1]);
    __nv_bfloat16 h2 = __float2bfloat16(vv[2]);
    __nv_bfloat16 h3 = __float2bfloat16(vv[3]);
    H0.x = h0; H0.y = h1; H1.x = h2; H1.y = h3;
    L0.x = __float2bfloat16(vv[0] - __bfloat162float(h0));
    L0.y = __float2bfloat16(vv[1] - __bfloat162float(h1));
    L1.x = __float2bfloat16(vv[2] - __bfloat162float(h2));
    L1.y = __float2bfloat16(vv[3] - __bfloat162float(h3));
    *reinterpret_cast<__nv_bfloat162*>(hi + i)     = H0;
    *reinterpret_cast<__nv_bfloat162*>(hi + i + 2) = H1;
    *reinterpret_cast<__nv_bfloat162*>(lo + i)     = L0;
    *reinterpret_cast<__nv_bfloat162*>(lo + i + 2) = L1;
}

// ---------------------------------------------------------------------------
__global__ __launch_bounds__(256) void wsplit(const float* __restrict__ WQ,
                                              const float* __restrict__ WK,
                                              const float* __restrict__ WV,
                                              const float* __restrict__ WO) {
    const int m = blockIdx.z;
    const float* W = (m == 0) ? WQ : (m == 1) ? WK : (m == 2) ? WV : WO;
    __nv_bfloat16* DH = g_wthi + (size_t)m * DM * DM;
    __nv_bfloat16* DL = g_wtlo + (size_t)m * DM * DM;

    __shared__ float t[32][33];
    const int c0 = blockIdx.x * 32, e0 = blockIdx.y * 32;
    const int tx = threadIdx.x, ty = threadIdx.y;

    #pragma unroll
    for (int j = 0; j < 4; j++) {
        int c = c0 + tx, e = e0 + ty + j * 8;
        size_t src = (m < 3)
            ? ((size_t)(c >> 6) * 65536 + (size_t)e * 64 + (c & 63))
            : ((size_t)e * 1024 + c);
        t[tx][ty + j * 8] = W[src];
    }
    __syncthreads();
    #pragma unroll
    for (int j = 0; j < 4; j++) {
        int e = e0 + tx, c = c0 + ty + j * 8;
        float v = t[ty + j * 8][tx];
        __nv_bfloat16 h = __float2bfloat16(v);
        DH[(size_t)c * 1024 + e] = h;
        DL[(size_t)c * 1024 + e] = __float2bfloat16(v - __bfloat162float(h));
    }
}

// ---------------------------------------------------------------------------
__global__ void vtrans() {
    __shared__ __nv_bfloat16 th[32][34];
    __shared__ __nv_bfloat16 tl[32][34];
    const int b  = blockIdx.z;
    const int s0 = blockIdx.x * 32;
    const int c0 = blockIdx.y * 32;
    const int tx = threadIdx.x, ty = threadIdx.y;

    #pragma unroll
    for (int j = 0; j < 4; j++) {
        int s = s0 + ty + j * 8, c = c0 + tx;
        size_t idx = ((size_t)b * 2048 + s) * DM + c;
        th[ty + j * 8][tx] = g_vhi[idx];
        tl[ty + j * 8][tx] = g_vlo[idx];
    }
    __syncthreads();
    #pragma unroll
    for (int j = 0; j < 4; j++) {
        int c = c0 + ty + j * 8, s = s0 + tx;
        size_t o = ((size_t)(b * 16 + (c >> 6)) * 64 + (c & 63)) * 2048 + s;
        g_vthi[o] = th[tx][ty + j * 8];
        g_vtlo[o] = tl[tx][ty + j * 8];
    }
}

// ---------------------------------------------------------------------------
// mma GEMM, 128x128 tile, now 2 CTAs/SM.
// ---------------------------------------------------------------------------
#define GS       80
#define GARR     10240
#define GBUF     40960
#define SMEM_G   81920

__global__ __launch_bounds__(256, 2) void gemm_mma(
    const __nv_bfloat16* __restrict__ Ahi, const __nv_bfloat16* __restrict__ Alo,
    const float* __restrict__ bQ, const float* __restrict__ bK,
    const float* __restrict__ bV, float* __restrict__ out_f32, int o_mode)
{
    extern __shared__ __align__(128) char sm[];
    const int tid  = threadIdx.x;
    const int lane = tid & 31, w = tid >> 5;
    const int wm = w >> 1, wn = w & 1;
    const int z  = blockIdx.z;
    const int bm = blockIdx.y * 128, bn = blockIdx.x * 128;

    const int slice = o_mode ? 3 : z;
    const __nv_bfloat16* Bh = g_wthi + (size_t)slice * DM * DM + (size_t)bn * DM;
    const __nv_bfloat16* Bl = g_wtlo + (size_t)slice * DM * DM + (size_t)bn * DM;
    const __nv_bfloat16* Ah = Ahi + (size_t)bm * DM;
    const __nv_bfloat16* Al = Alo + (size_t)bm * DM;
    const float* bias = o_mode ? bQ : (z == 0 ? bQ : (z == 1 ? bK : bV));
    __nv_bfloat16* Ohi = (z == 0) ? g_qhi : (z == 1) ? g_khi : g_vhi;
    __nv_bfloat16* Olo = (z == 0) ? g_qlo : (z == 1) ? g_klo : g_vlo;

    const unsigned sbase = smem_u32(sm);

    float acc[2][8][4];
    #pragma unroll
    for (int i = 0; i < 2; i++)
        #pragma unroll
        for (int j = 0; j < 8; j++)
            #pragma unroll
            for (int e = 0; e < 4; e++) acc[i][j][e] = 0.f;

    const __nv_bfloat16* srcs[4] = {Ah, Al, Bh, Bl};

    auto fill = [&](int buf, int k0) {
        #pragma unroll
        for (int a = 0; a < 4; a++) {
            unsigned ab = sbase + buf * GBUF + a * GARR;
            #pragma unroll
            for (int i = 0; i < 2; i++) {
                int c = tid + i * 256;
                int row = c >> 2, q = c & 3;
                unsigned sa = ab + row * GS + q * 16;
                CPASYNC16(sa, srcs[a] + (size_t)row * DM + k0 + q * 8);
            }
        }
        CPCOMMIT();
    };

    fill(0, 0);
    #pragma unroll 1
    for (int ci = 0; ci < 32; ci++) {
        const int buf = ci & 1;
        if (ci + 1 < 32) { fill(buf ^ 1, (ci + 1) * 32); CPWAIT1(); }
        else             { CPWAIT0(); }
        __syncthreads();

        const unsigned Ab = sbase + buf * GBUF;
        const unsigned Bb = Ab + 2 * GARR;
        #pragma unroll
        for (int ks = 0; ks < 2; ks++) {
            const int kb = ks * 32;
            unsigned ah[2][4], al[2][4];
            #pragma unroll
            for (int i = 0; i < 2; i++) {
                unsigned aaddr = Ab + (wm * 32 + i * 16 + (lane & 15)) * GS + kb
                                 + ((lane >> 4) & 1) * 16;
                ldmx4(aaddr, ah[i][0], ah[i][1], ah[i][2], ah[i][3]);
                ldmx4(aaddr + GARR, al[i][0], al[i][1], al[i][2], al[i][3]);
            }
            #pragma unroll
            for (int jj = 0; jj < 4; jj++) {
                unsigned baddr = Bb + (wn * 64 + jj * 16 + (lane & 7)
                                 + ((lane >> 4) & 1) * 8) * GS + kb
                                 + ((lane >> 3) & 1) * 16;
                unsigned bh0, bh1, bh2, bh3, bl0, bl1, bl2, bl3;
                ldmx4(baddr, bh0, bh1, bh2, bh3);
                ldmx4(baddr + GARR, bl0, bl1, bl2, bl3);
                #pragma unroll
                for (int i = 0; i < 2; i++) {
                    mmabf16(acc[i][jj * 2],     ah[i], bh0, bh1);
                    mmabf16(acc[i][jj * 2],     al[i], bh0, bh1);
                    mmabf16(acc[i][jj * 2],     ah[i], bl0, bl1);
                    mmabf16(acc[i][jj * 2 + 1], ah[i], bh2, bh3);
                    mmabf16(acc[i][jj * 2 + 1], al[i], bh2, bh3);
                    mmabf16(acc[i][jj * 2 + 1], ah[i], bl2, bl3);
                }
            }
        }
        __syncthreads();
    }

    #pragma unroll
    for (int i = 0; i < 2; i++) {
        const int row = bm + wm * 32 + i * 16 + (lane >> 2);
        #pragma unroll
        for (int j = 0; j < 8; j++) {
            const int col = bn + wn * 64 + j * 8 + (lane & 3) * 2;
            float v0 = acc[i][j][0] + bias[col];
            float v1 = acc[i][j][1] + bias[col + 1];
            float v2 = acc[i][j][2] + bias[col];
            float v3 = acc[i][j][3] + bias[col + 1];
            if (o_mode) {
                float2 a = {v0, v1}, b2 = {v2, v3};
                *reinterpret_cast<float2*>(&out_f32[(size_t)row * DM + col]) = a;
                *reinterpret_cast<float2*>(&out_f32[(size_t)(row + 8) * DM + col]) = b2;
            } else {
                __nv_bfloat162 h2, l2;
                h2.x = __float2bfloat16(v0); h2.y = __float2bfloat16(v1);
                l2.x = __float2bfloat16(v0 - __bfloat162float(h2.x));
                l2.y = __float2bfloat16(v1 - __bfloat162float(h2.y));
                *reinterpret_cast<__nv_bfloat162*>(&Ohi[(size_t)row * DM + col]) = h2;
                *reinterpret_cast<__nv_bfloat162*>(&Olo[(size_t)row * DM + col]) = l2;
                h2.x = __float2bfloat16(v2); h2.y = __float2bfloat16(v3);
                l2.x = __float2bfloat16(v2 - __bfloat162float(h2.x));
                l2.y = __float2bfloat16(v3 - __bfloat162float(h2.y));
                *reinterpret_cast<__nv_bfloat162*>(&Ohi[(size_t)(row + 8) * DM + col]) = h2;
                *reinterpret_cast<__nv_bfloat162*>(&Olo[(size_t)(row + 8) * DM + col]) = l2;
            }
        }
    }
}

// ---------------------------------------------------------------------------
// flash attention: BQ=128 (8 warps), key tiles of 64, double-buffered K/V.
// smem: Qh,Ql (128x144 each) + 2 bufs x {Kh,Kl,Vh,Vl} (64x144 each) = 108KB
// ---------------------------------------------------------------------------
#define AS      144
#define AARR    9216             // 64*144
#define QARR    18432            // 128*144
#define KVBASE  (2 * QARR)       // 36864
#define SMEM_A  110592

__global__ __launch_bounds__(256, 2) void attn_mma()
{
    extern __shared__ __align__(128) char sm[];
    const int tid = threadIdx.x, lane = tid & 31, w = tid >> 5;
    const int qt = (int)gridDim.x - 1 - (int)blockIdx.x;   // big tiles first
    const int bh = blockIdx.y;
    const int b = bh >> 4, h = bh & 15;

    const unsigned sb = smem_u32(sm);
    const size_t qrow0 = (size_t)b * 2048 + (size_t)qt * 128;
    const size_t hoff  = (size_t)h * 64;

    // ---- Q tile load (hi+lo): 128 rows ----
    {
        const __nv_bfloat16* qh = g_qhi + qrow0 * DM + hoff;
        const __nv_bfloat16* ql = g_qlo + qrow0 * DM + hoff;
        #pragma unroll
        for (int i = 0; i < 8; i++) {
            int c = tid + i * 256;            // 0..2047
            int a = c >> 10, r = (c >> 3) & 127, q = c & 7;
            unsigned sa = sb + a * QARR + r * AS + q * 16;
            const __nv_bfloat16* src = a ? ql : qh;
            CPASYNC16(sa, src + (size_t)r * DM + q * 8);
        }
        CPCOMMIT(); CPWAIT0();
        __syncthreads();
    }
    unsigned qfh[4][4], qfl[4][4];
    #pragma unroll
    for (int ks = 0; ks < 4; ks++) {
        unsigned aaddr = sb + (w * 16 + (lane & 15)) * AS + ks * 32
                         + ((lane >> 4) & 1) * 16;
        ldmx4(aaddr, qfh[ks][0], qfh[ks][1], qfh[ks][2], qfh[ks][3]);
        ldmx4(aaddr + QARR, qfl[ks][0], qfl[ks][1], qfl[ks][2], qfl[ks][3]);
    }

    float o[8][4];
    #pragma unroll
    for (int j = 0; j < 8; j++)
        #pragma unroll
        for (int e = 0; e < 4; e++) o[j][e] = 0.f;
    float m0 = -1e30f, m1 = -1e30f, l0 = 0.f, l1 = 0.f;

    const __nv_bfloat16* kh = g_khi + (size_t)b * 2048 * DM + hoff;
    const __nv_bfloat16* kl = g_klo + (size_t)b * 2048 * DM + hoff;
    const __nv_bfloat16* vh = g_vthi + (size_t)bh * 64 * 2048;
    const __nv_bfloat16* vl = g_vtlo + (size_t)bh * 64 * 2048;

    const int nk = 2 * qt + 2;    // causal key tiles of 64

    // fill KV tile kt into buf
    auto fillkv = [&](int buf, int kt) {
        #pragma unroll
        for (int i = 0; i < 8; i++) {
            int c = tid + i * 256;            // 0..2047
            int a = c >> 9;                   // 0=Kh 1=Kl 2=Vh 3=Vl
            int r = (c >> 3) & 63, q = c & 7;
            unsigned sa = sb + KVBASE + buf * 4 * AARR + a * AARR + r * AS + q * 16;
            const __nv_bfloat16* src;
            size_t off;
            if (a < 2) { src = (a == 0) ? kh : kl; off = (size_t)(kt * 64 + r) * DM + q * 8; }
            else       { src = (a == 2) ? vh : vl; off = (size_t)r * 2048 + kt * 64 + q * 8; }
            CPASYNC16(sa, src + off);
        }
        CPCOMMIT();
    };

    fillkv(0, 0);
    #pragma unroll 1
    for (int kt = 0; kt < nk; kt++) {
        const int buf = kt & 1;
        if (kt + 1 < nk) { fillkv(buf ^ 1, kt + 1); CPWAIT1(); }
        else             { CPWAIT0(); }
        __syncthreads();

        const unsigned Khb = sb + KVBASE + buf * 4 * AARR;
        const unsigned Vhb = Khb + 2 * AARR;

        // ---- S = Q K^T (3-split) ----
        float s[8][4];
        #pragma unroll
        for (int j = 0; j < 8; j++)
            #pragma unroll
            for (int e = 0; e < 4; e++) s[j][e] = 0.f;

        #pragma unroll
        for (int ks = 0; ks < 4; ks++) {
            const int kb = ks * 32;
            #pragma unroll
            for (int jj = 0; jj < 4; jj++) {
                unsigned baddr = Khb + (jj * 16 + (lane & 7) + ((lane >> 4) & 1) * 8) * AS
                                 + kb + ((lane >> 3) & 1) * 16;
                unsigned b0, b1, b2, b3, c0, c1, c2, c3;
                ldmx4(baddr, b0, b1, b2, b3);
                ldmx4(baddr + AARR, c0, c1, c2, c3);
                mmabf16(s[jj * 2],     qfh[ks], b0, b1);
                mmabf16(s[jj * 2],     qfl[ks], b0, b1);
                mmabf16(s[jj * 2],     qfh[ks], c0, c1);
                mmabf16(s[jj * 2 + 1], qfh[ks], b2, b3);
                mmabf16(s[jj * 2 + 1], qfl[ks], b2, b3);
                mmabf16(s[jj * 2 + 1], qfh[ks], c2, c3);
            }
        }

        #pragma unroll
        for (int j = 0; j < 8; j++)
            #pragma unroll
            for (int e = 0; e < 4; e++) s[j][e] *= 0.125f;

        // causal mask: only the last two key tiles intersect the diagonal
        if (kt >= 2 * qt) {
            const int r0 = qt * 128 + w * 16 + (lane >> 2), r1 = r0 + 8;
            #pragma unroll
            for (int j = 0; j < 8; j++) {
                const int cb = kt * 64 + j * 8 + (lane & 3) * 2;
                if (cb     > r0) s[j][0] = -1e5f;
                if (cb + 1 > r0) s[j][1] = -1e5f;
                if (cb     > r1) s[j][2] = -1e5f;
                if (cb + 1 > r1) s[j][3] = -1e5f;
            }
        }
        float mx0 = -1e30f, mx1 = -1e30f;
        #pragma unroll
        for (int j = 0; j < 8; j++) {
            mx0 = fmaxf(mx0, fmaxf(s[j][0], s[j][1]));
            mx1 = fmaxf(mx1, fmaxf(s[j][2], s[j][3]));
        }
        mx0 = fmaxf(mx0, __shfl_xor_sync(0xffffffffu, mx0, 1));
        mx0 = fmaxf(mx0, __shfl_xor_sync(0xffffffffu, mx0, 2));
        mx1 = fmaxf(mx1, __shfl_xor_sync(0xffffffffu, mx1, 1));
        mx1 = fmaxf(mx1, __shfl_xor_sync(0xffffffffu, mx1, 2));
        const float nm0 = fmaxf(m0, mx0), nm1 = fmaxf(m1, mx1);
        const float a0 = __expf(m0 - nm0), a1 = __expf(m1 - nm1);
        m0 = nm0; m1 = nm1;
        float sum0 = 0.f, sum1 = 0.f;
        #pragma unroll
        for (int j = 0; j < 8; j++) {
            s[j][0] = __expf(s[j][0] - nm0); sum0 += s[j][0];
            s[j][1] = __expf(s[j][1] - nm0); sum0 += s[j][1];
            s[j][2] = __expf(s[j][2] - nm1); sum1 += s[j][2];
            s[j][3] = __expf(s[j][3] - nm1); sum1 += s[j][3];
        }
        sum0 += __shfl_xor_sync(0xffffffffu, sum0, 1);
        sum0 += __shfl_xor_sync(0xffffffffu, sum0, 2);
        sum1 += __shfl_xor_sync(0xffffffffu, sum1, 1);
        sum1 += __shfl_xor_sync(0xffffffffu, sum1, 2);
        l0 = l0 * a0 + sum0;
        l1 = l1 * a1 + sum1;
        #pragma unroll
        for (int j = 0; j < 8; j++) {
            o[j][0] *= a0; o[j][1] *= a0; o[j][2] *= a1; o[j][3] *= a1;
        }

        // ---- O += P V (3-split) ----
        #pragma unroll
        for (int kk = 0; kk < 4; kk++) {
            const int t0 = kk * 2, t1 = kk * 2 + 1;
            unsigned pah[4], pal[4];
            {
                float v0 = s[t0][0], v1 = s[t0][1];
                pah[0] = pack_bf2(v0, v1);
                pal[0] = pack_bf2(v0 - __bfloat162float(__float2bfloat16(v0)),
                                  v1 - __bfloat162float(__float2bfloat16(v1)));
                v0 = s[t0][2]; v1 = s[t0][3];
                pah[1] = pack_bf2(v0, v1);
                pal[1] = pack_bf2(v0 - __bfloat162float(__float2bfloat16(v0)),
                                  v1 - __bfloat162float(__float2bfloat16(v1)));
                v0 = s[t1][0]; v1 = s[t1][1];
                pah[2] = pack_bf2(v0, v1);
                pal[2] = pack_bf2(v0 - __bfloat162float(__float2bfloat16(v0)),
                                  v1 - __bfloat162float(__float2bfloat16(v1)));
                v0 = s[t1][2]; v1 = s[t1][3];
                pah[3] = pack_bf2(v0, v1);
                pal[3] = pack_bf2(v0 - __bfloat162float(__float2bfloat16(v0)),
                                  v1 - __bfloat162float(__float2bfloat16(v1)));
            }
            #pragma unroll
            for (int jj = 0; jj < 4; jj++) {
                unsigned baddr = Vhb + (jj * 16 + (lane & 7) + ((lane >> 4) & 1) * 8) * AS
                                 + kk * 32 + ((lane >> 3) & 1) * 16;
                unsigned b0, b1, b2, b3, c0, c1, c2, c3;
                ldmx4(baddr, b0, b1, b2, b3);
                ldmx4(baddr + AARR, c0, c1, c2, c3);
                mmabf16(o[jj * 2],     pah, b0, b1);
                mmabf16(o[jj * 2],     pal, b0, b1);
                mmabf16(o[jj * 2],     pah, c0, c1);
                mmabf16(o[jj * 2 + 1], pah, b2, b3);
                mmabf16(o[jj * 2 + 1], pal, b2, b3);
                mmabf16(o[jj * 2 + 1], pah, c2, c3);
            }
        }
        __syncthreads();   // all reads of buf done before it is refilled
    }

    // ---- finalize + write z ----
    const float inv0 = 1.0f / l0, inv1 = 1.0f / l1;
    const size_t row0 = qrow0 + w * 16 + (lane >> 2);
    #pragma unroll
    for (int j = 0; j < 8; j++) {
        const size_t col = hoff + j * 8 + (lane & 3) * 2;
        float v0 = o[j][0] * inv0, v1 = o[j][1] * inv0;
        float v2 = o[j][2] * inv1, v3 = o[j][3] * inv1;
        __nv_bfloat162 h2, l2;
        h2.x = __float2bfloat16(v0); h2.y = __float2bfloat16(v1);
        l2.x = __float2bfloat16(v0 - __bfloat162float(h2.x));
        l2.y = __float2bfloat16(v1 - __bfloat162float(h2.y));
        *reinterpret_cast<__nv_bfloat162*>(&g_zhi[row0 * DM + col]) = h2;
        *reinterpret_cast<__nv_bfloat162*>(&g_zlo[row0 * DM + col]) = l2;
        h2.x = __float2bfloat16(v2); h2.y = __float2bfloat16(v3);
        l2.x = __float2bfloat16(v2 - __bfloat162float(h2.x));
        l2.y = __float2bfloat16(v3 - __bfloat162float(h2.y));
        *reinterpret_cast<__nv_bfloat162*>(&g_zhi[(row0 + 8) * DM + col]) = h2;
        *reinterpret_cast<__nv_bfloat162*>(&g_zlo[(row0 + 8) * DM + col]) = l2;
    }
}

// ---------------------------------------------------------------------------
extern "C" void kernel_launch(void* const* d_in, const int* in_sizes, int n_in,
                              void* d_out, int out_size)
{
    (void)in_sizes; (void)n_in; (void)out_size;
    const float* x  = (const float*)d_in[0];
    const float* WQ = (const float*)d_in[1];
    const float* bQ = (const float*)d_in[2];
    const float* WK = (const float*)d_in[3];
    const float* bK = (const float*)d_in[4];
    const float* WV = (const float*)d_in[5];
    const float* bV = (const float*)d_in[6];
    const float* WO = (const float*)d_in[7];
    const float* bO = (const float*)d_in[8];
    float* out = (float*)d_out;

    cudaFuncSetAttribute(gemm_mma, cudaFuncAttributeMaxDynamicSharedMemorySize, SMEM_G);
    cudaFuncSetAttribute(attn_mma, cudaFuncAttributeMaxDynamicSharedMemorySize, SMEM_A);

    __nv_bfloat16 *xhi, *xlo, *zhi, *zlo;
    cudaGetSymbolAddress((void**)&xhi, g_xhi);
    cudaGetSymbolAddress((void**)&xlo, g_xlo);
    cudaGetSymbolAddress((void**)&zhi, g_zhi);
    cudaGetSymbolAddress((void**)&zlo, g_zlo);

    fsplit<<<(BSROWS * DM) / 1024, 256>>>(x, xhi, xlo);
    wsplit<<<dim3(32, 32, 4), dim3(32, 8)>>>(WQ, WK, WV, WO);

    gemm_mma<<<dim3(8, 64, 3), 256, SMEM_G>>>(xhi, xlo, bQ, bK, bV, nullptr, 0);

    vtrans<<<dim3(64, 32, 4), dim3(32, 8)>>>();

    attn_mma<<<dim3(16, 64), 256, SMEM_A>>>();

    gemm_mma<<<dim3(8, 64, 1), 256, SMEM_G>>>(zhi, zlo, bO, bO, bO, out, 1);
}